// round 9
// baseline (speedup 1.0000x reference)
#include <cuda_runtime.h>

#define NANCH 8400
#define BATCH 32
#define NCLS  80
#define BINS  16
#define LOG2E 1.44269504f
#define LN2   0.69314718f

// [0]=cls_sum [1]=iou_sum [2]=dfl_sum [3]=pos_count
__device__ double g_acc[4];
__device__ unsigned int g_done;

// focal t=0 element (scaled): sigmoid(s)^2 * log2(1+e^s); full term = 0.75*ln2 * this
__device__ __forceinline__ float cls_neg_raw(float s) {
    float z  = s * LOG2E;
    float e  = exp2f(z);
    float L  = __log2f(1.f + e);
    float q  = exp2f(z - L);             // sigmoid(s)
    return q * q * L;
}

template<int HW, int W, int STRIDE, int AOFS>
__device__ __forceinline__ void process_scale(
    const float* __restrict__ p, const float* __restrict__ gtb,
    const int* __restrict__ gtl, const int* __restrict__ mind,
    int tile, float& cls_s, float& iou_s, float& dfl_s, int& cnt)
{
    const int i   = tile * 256 + threadIdx.x;
    const int img = i / HW;
    const int hw  = i - img * HW;

    const int ind = mind[img * NANCH + AOFS + hw];   // issue early

    const float* base  = p + (size_t)img * 144 * HW + hw;
    const float* cbase = base + 64 * HW;

    // ---------- classification: 80 channels, compile-time imm offsets ----------
    float c0 = 0.f, c1 = 0.f, c2 = 0.f, c3 = 0.f;
    #pragma unroll
    for (int c = 0; c < NCLS; c += 4) {
        float s0 = cbase[(c + 0) * HW];
        float s1 = cbase[(c + 1) * HW];
        float s2 = cbase[(c + 2) * HW];
        float s3 = cbase[(c + 3) * HW];
        c0 += cls_neg_raw(s0);
        c1 += cls_neg_raw(s1);
        c2 += cls_neg_raw(s2);
        c3 += cls_neg_raw(s3);
    }
    cls_s = ((c0 + c1) + (c2 + c3)) * (0.75f * LN2);

    // ---------- positives: warp-cooperative, no barriers ----------
    unsigned mask = __ballot_sync(0xffffffffu, ind >= 0);
    cnt = __popc(mask);                       // identical on all lanes of the warp

    const int lane = threadIdx.x & 31;
    const int kk   = lane >> 3;               // side 0..3 (l,t,r,b)
    const int tt   = lane & 7;                // bin pair: handles bins tt and tt+8
    // loop-invariant per-lane DFL channel offsets (compile-time HW)
    const int ch1 = (kk * BINS + tt) * HW;
    const int ch2 = (kk * BINS + tt + 8) * HW;

    while (mask) {
        const int src = __ffs(mask) - 1;
        mask &= mask - 1;

        const int s_img = __shfl_sync(0xffffffffu, img, src);
        const int s_hw  = __shfl_sync(0xffffffffu, hw,  src);
        const int s_ind = __shfl_sync(0xffffffffu, ind, src);

        const float* b2  = p + (size_t)s_img * 144 * HW + s_hw;
        const float* tb4 = gtb + (size_t)(s_img * 32 + s_ind) * 4;
        // uniform address -> single broadcast load per word
        const float tx1 = __ldg(tb4 + 0), ty1 = __ldg(tb4 + 1);
        const float tx2 = __ldg(tb4 + 2), ty2 = __ldg(tb4 + 3);

        const int wy = s_hw / W, wx = s_hw - wy * W;
        const float gx = (wx + 0.5f) * (float)STRIDE;
        const float gy = (wy + 0.5f) * (float)STRIDE;

        // this lane's side target
        float tgt_k = (kk == 0) ? fmaxf(gx - tx1, 0.f)
                    : (kk == 1) ? fmaxf(gy - ty1, 0.f)
                    : (kk == 2) ? fmaxf(tx2 - gx, 0.f)
                                : fmaxf(ty2 - gy, 0.f);
        float tb = fminf(tgt_k * (1.f / (float)STRIDE), 15.f - 1e-6f);
        int   lo = (int)tb;
        int   hi = min(lo + 1, BINS - 1);
        float aa = tb - (float)lo;

        // 2 scattered loads per lane -> 64-wide MLP per warp
        float v1 = b2[ch1];
        float v2 = b2[ch2];
        float e1 = __expf(v1);
        float e2 = __expf(v2);
        float S  = e1 + e2;
        float E  = e1 * (float)tt + e2 * (float)(tt + 8);
        float vlo = ((tt     == lo) ? v1 : 0.f) + ((tt + 8 == lo) ? v2 : 0.f);
        float vhi = ((tt     == hi) ? v1 : 0.f) + ((tt + 8 == hi) ? v2 : 0.f);

        // xor-butterfly reduce within each 8-lane group
        #pragma unroll
        for (int o = 4; o > 0; o >>= 1) {
            S   += __shfl_xor_sync(0xffffffffu, S,   o);
            E   += __shfl_xor_sync(0xffffffffu, E,   o);
            vlo += __shfl_xor_sync(0xffffffffu, vlo, o);
            vhi += __shfl_xor_sync(0xffffffffu, vhi, o);
        }

        float dk = __fdividef(E, S) * (float)STRIDE;
        if (tt == 0) {
            float lS = __logf(S);
            dfl_s -= (1.f - aa) * (vlo - lS) + aa * (vhi - lS);
        }

        // gather the 4 distances
        float d0 = __shfl_sync(0xffffffffu, dk, 0);
        float d1 = __shfl_sync(0xffffffffu, dk, 8);
        float d2 = __shfl_sync(0xffffffffu, dk, 16);
        float d3 = __shfl_sync(0xffffffffu, dk, 24);

        if (lane == 0) {
            float px1 = gx - d0, py1 = gy - d1;
            float px2 = gx + d2, py2 = gy + d3;
            float ix1 = fmaxf(px1, tx1), iy1 = fmaxf(py1, ty1);
            float ix2 = fminf(px2, tx2), iy2 = fminf(py2, ty2);
            float inter  = fmaxf(ix2 - ix1, 0.f) * fmaxf(iy2 - iy1, 0.f);
            float area_p = fmaxf(px2 - px1, 0.f) * fmaxf(py2 - py1, 0.f);
            float area_t = fmaxf(tx2 - tx1, 0.f) * fmaxf(ty2 - ty1, 0.f);
            float iou = inter / (area_p + area_t - inter + 1e-7f);
            iou_s += 1.f - iou;
        } else if (lane == 8) {
            // label fixup: swap t=0 -> t=1 element on the label channel
            int lbl = gtl[s_img * 32 + s_ind];
            float s = b2[(64 + lbl) * HW];
            float z = s * LOG2E;
            float e = exp2f(z);
            float L = __log2f(1.f + e);
            float q = exp2f(z - L);
            float elem0 = 0.75f * LN2 * q * q * L;
            float elem1 = 0.25f * exp2f(-2.f * L) * (L * LN2 - s);
            cls_s += elem1 - elem0;
        }
    }
}

__global__ void __launch_bounds__(256, 8) yolo_loss_kernel(
    const float* __restrict__ p0, const float* __restrict__ p1, const float* __restrict__ p2,
    const float* __restrict__ gtb, const int* __restrict__ gtl, const int* __restrict__ mind,
    float* __restrict__ out, int out_n)
{
    float cls_s = 0.f, iou_s = 0.f, dfl_s = 0.f;
    int cnt = 0;

    const int tile = blockIdx.x;
    if (tile < 800) {
        process_scale<6400, 80,  8, 0>(p0, gtb, gtl, mind, tile,        cls_s, iou_s, dfl_s, cnt);
    } else if (tile < 1000) {
        process_scale<1600, 40, 16, 6400>(p1, gtb, gtl, mind, tile - 800,  cls_s, iou_s, dfl_s, cnt);
    } else {
        process_scale< 400, 20, 32, 8000>(p2, gtb, gtl, mind, tile - 1000, cls_s, iou_s, dfl_s, cnt);
    }

    // ---------- block reduction ----------
    #pragma unroll
    for (int o = 16; o > 0; o >>= 1) {
        cls_s += __shfl_down_sync(0xffffffffu, cls_s, o);
        iou_s += __shfl_down_sync(0xffffffffu, iou_s, o);
        dfl_s += __shfl_down_sync(0xffffffffu, dfl_s, o);
    }

    __shared__ float sc[8], si[8], sd[8];
    __shared__ int   sp[8];
    int lane = threadIdx.x & 31;
    int warp = threadIdx.x >> 5;
    if (lane == 0) { sc[warp] = cls_s; si[warp] = iou_s; sd[warp] = dfl_s; sp[warp] = cnt; }
    __syncthreads();

    if (warp == 0 && lane == 0) {
        cls_s = 0.f; iou_s = 0.f; dfl_s = 0.f; cnt = 0;
        #pragma unroll
        for (int w = 0; w < 8; ++w) {
            cls_s += sc[w]; iou_s += si[w]; dfl_s += sd[w]; cnt += sp[w];
        }

        atomicAdd(&g_acc[0], (double)cls_s);
        atomicAdd(&g_acc[1], (double)iou_s);
        atomicAdd(&g_acc[2], (double)dfl_s);
        atomicAdd(&g_acc[3], (double)cnt);

        __threadfence();
        unsigned int ticket = atomicAdd(&g_done, 1u);
        if (ticket == gridDim.x - 1) {
            double v0 = atomicAdd(&g_acc[0], 0.0);
            double v1 = atomicAdd(&g_acc[1], 0.0);
            double v2 = atomicAdd(&g_acc[2], 0.0);
            double v3 = atomicAdd(&g_acc[3], 0.0);
            double np = v3 < 1.0 ? 1.0 : v3;
            double total = v0 / np + 7.5 * v1 / np + 1.5 * v2 / (np * 4.0);
            for (int i = 0; i < out_n; ++i) out[i] = (float)total;
            g_acc[0] = 0.0; g_acc[1] = 0.0; g_acc[2] = 0.0; g_acc[3] = 0.0;
            __threadfence();
            g_done = 0u;
        }
    }
}

extern "C" void kernel_launch(void* const* d_in, const int* in_sizes, int n_in,
                              void* d_out, int out_size) {
    const float* p0   = (const float*)d_in[0];
    const float* p1   = (const float*)d_in[1];
    const float* p2   = (const float*)d_in[2];
    const float* gtb  = (const float*)d_in[3];
    const int*   gtl  = (const int*)d_in[4];
    const int*   mind = (const int*)d_in[5];
    float* out = (float*)d_out;

    // 800 + 200 + 50 = 1050 blocks; one wave at 8 blocks/SM
    yolo_loss_kernel<<<1050, 256>>>(p0, p1, p2, gtb, gtl, mind, out, out_size);
}

// round 10
// speedup vs baseline: 1.0571x; 1.0571x over previous
#include <cuda_runtime.h>

#define NANCH 8400
#define BATCH 32
#define NCLS  80
#define BINS  16
#define LOG2E 1.44269504f
#define LN2   0.69314718f

// [0]=cls_sum [1]=iou_sum [2]=dfl_sum [3]=pos_count
__device__ double g_acc[4];
__device__ unsigned int g_done;

__device__ __forceinline__ float tanh_fast(float x) {
    float y;
    asm("tanh.approx.f32 %0, %1;" : "=f"(y) : "f"(x));
    return y;
}

// returns sigmoid(s)^2 * log2(sigmoid(-s));  focal t=0 elem = -0.75*ln2 * this
// 2 MUFU (TANH, LG2) + ~5 fma ops
__device__ __forceinline__ float cls_neg_raw(float s) {
    float t = tanh_fast(0.5f * s);
    float u = 0.5f - 0.5f * t;           // sigmoid(-s)
    float p = 0.5f + 0.5f * t;           // sigmoid(s)
    return p * p * __log2f(u);
}

template<int HW, int W, int STRIDE, int AOFS>
__device__ __forceinline__ void process_scale(
    const float* __restrict__ p, const float* __restrict__ gtb,
    const int* __restrict__ gtl, const int* __restrict__ mind,
    int tile, float& cls_s, float& iou_s, float& dfl_s, int& pos_flag)
{
    const int i   = tile * 256 + threadIdx.x;
    const int img = i / HW;
    const int hw  = i - img * HW;

    const int ind = mind[img * NANCH + AOFS + hw];   // issue early

    const float* base  = p + (size_t)img * 144 * HW + hw;
    const float* cbase = base + 64 * HW;

    // ---------- classification: 80 channels, compile-time imm offsets ----------
    float c0 = 0.f, c1 = 0.f, c2 = 0.f, c3 = 0.f;
    #pragma unroll
    for (int c = 0; c < NCLS; c += 4) {
        float s0 = cbase[(c + 0) * HW];
        float s1 = cbase[(c + 1) * HW];
        float s2 = cbase[(c + 2) * HW];
        float s3 = cbase[(c + 3) * HW];
        c0 += cls_neg_raw(s0);
        c1 += cls_neg_raw(s1);
        c2 += cls_neg_raw(s2);
        c3 += cls_neg_raw(s3);
    }
    cls_s = ((c0 + c1) + (c2 + c3)) * (-0.75f * LN2);

    // ---------- positives: inline, divergent (~5% of lanes) ----------
    if (ind >= 0) {
        pos_flag = 1;
        int lbl = gtl[img * 32 + ind];

        // swap t=0 -> t=1 element on the label channel (same tanh identity)
        {
            float s = cbase[lbl * HW];
            float t = tanh_fast(0.5f * s);
            float u = 0.5f - 0.5f * t;
            float q = 0.5f + 0.5f * t;
            float elem0 = -0.75f * LN2 * q * q * __log2f(u);
            float elem1 = -0.25f * LN2 * u * u * __log2f(q);
            cls_s += elem1 - elem0;
        }

        const float* tb4 = gtb + (size_t)(img * 32 + ind) * 4;
        float tx1 = tb4[0], ty1 = tb4[1], tx2 = tb4[2], ty2 = tb4[3];

        int wy = hw / W, wx = hw - wy * W;
        float gx = (wx + 0.5f) * (float)STRIDE;
        float gy = (wy + 0.5f) * (float)STRIDE;

        float tgt[4] = { fmaxf(gx - tx1, 0.f), fmaxf(gy - ty1, 0.f),
                         fmaxf(tx2 - gx, 0.f), fmaxf(ty2 - gy, 0.f) };
        float d[4];

        #pragma unroll
        for (int k = 0; k < 4; ++k) {
            float tb = fminf(tgt[k] * (1.f / (float)STRIDE), 15.f - 1e-6f);
            int   lo = (int)tb;
            int   hi = min(lo + 1, BINS - 1);
            float aa = tb - (float)lo;

            float S = 0.f, E = 0.f, vlo = 0.f, vhi = 0.f;
            #pragma unroll
            for (int jj = 0; jj < BINS; ++jj) {
                float v = base[(k * BINS + jj) * HW];
                float e = __expf(v);
                S += e;
                E += e * (float)jj;
                vlo = (jj == lo) ? v : vlo;
                vhi = (jj == hi) ? v : vhi;
            }
            d[k] = __fdividef(E, S) * (float)STRIDE;
            float lS = __logf(S);
            dfl_s -= (1.f - aa) * (vlo - lS) + aa * (vhi - lS);
        }

        float px1 = gx - d[0], py1 = gy - d[1];
        float px2 = gx + d[2], py2 = gy + d[3];
        float ix1 = fmaxf(px1, tx1), iy1 = fmaxf(py1, ty1);
        float ix2 = fminf(px2, tx2), iy2 = fminf(py2, ty2);
        float inter  = fmaxf(ix2 - ix1, 0.f) * fmaxf(iy2 - iy1, 0.f);
        float area_p = fmaxf(px2 - px1, 0.f) * fmaxf(py2 - py1, 0.f);
        float area_t = fmaxf(tx2 - tx1, 0.f) * fmaxf(ty2 - ty1, 0.f);
        float iou = inter / (area_p + area_t - inter + 1e-7f);
        iou_s = 1.f - iou;
    }
}

__global__ void __launch_bounds__(256, 8) yolo_loss_kernel(
    const float* __restrict__ p0, const float* __restrict__ p1, const float* __restrict__ p2,
    const float* __restrict__ gtb, const int* __restrict__ gtl, const int* __restrict__ mind,
    float* __restrict__ out, int out_n)
{
    float cls_s = 0.f, iou_s = 0.f, dfl_s = 0.f;
    int pos_flag = 0;

    const int tile = blockIdx.x;
    if (tile < 800) {
        process_scale<6400, 80,  8, 0>(p0, gtb, gtl, mind, tile,        cls_s, iou_s, dfl_s, pos_flag);
    } else if (tile < 1000) {
        process_scale<1600, 40, 16, 6400>(p1, gtb, gtl, mind, tile - 800,  cls_s, iou_s, dfl_s, pos_flag);
    } else {
        process_scale< 400, 20, 32, 8000>(p2, gtb, gtl, mind, tile - 1000, cls_s, iou_s, dfl_s, pos_flag);
    }

    // ---------- block reduction ----------
    int cnt = __popc(__ballot_sync(0xffffffffu, pos_flag));
    #pragma unroll
    for (int o = 16; o > 0; o >>= 1) {
        cls_s += __shfl_down_sync(0xffffffffu, cls_s, o);
        iou_s += __shfl_down_sync(0xffffffffu, iou_s, o);
        dfl_s += __shfl_down_sync(0xffffffffu, dfl_s, o);
    }

    __shared__ float sc[8], si[8], sd[8];
    __shared__ int   sp[8];
    int lane = threadIdx.x & 31;
    int warp = threadIdx.x >> 5;
    if (lane == 0) { sc[warp] = cls_s; si[warp] = iou_s; sd[warp] = dfl_s; sp[warp] = cnt; }
    __syncthreads();

    if (warp == 0 && lane == 0) {
        cls_s = 0.f; iou_s = 0.f; dfl_s = 0.f; cnt = 0;
        #pragma unroll
        for (int w = 0; w < 8; ++w) {
            cls_s += sc[w]; iou_s += si[w]; dfl_s += sd[w]; cnt += sp[w];
        }

        atomicAdd(&g_acc[0], (double)cls_s);
        atomicAdd(&g_acc[1], (double)iou_s);
        atomicAdd(&g_acc[2], (double)dfl_s);
        atomicAdd(&g_acc[3], (double)cnt);

        __threadfence();
        unsigned int ticket = atomicAdd(&g_done, 1u);
        if (ticket == gridDim.x - 1) {
            double v0 = atomicAdd(&g_acc[0], 0.0);
            double v1 = atomicAdd(&g_acc[1], 0.0);
            double v2 = atomicAdd(&g_acc[2], 0.0);
            double v3 = atomicAdd(&g_acc[3], 0.0);
            double np = v3 < 1.0 ? 1.0 : v3;
            double total = v0 / np + 7.5 * v1 / np + 1.5 * v2 / (np * 4.0);
            for (int i = 0; i < out_n; ++i) out[i] = (float)total;
            g_acc[0] = 0.0; g_acc[1] = 0.0; g_acc[2] = 0.0; g_acc[3] = 0.0;
            __threadfence();
            g_done = 0u;
        }
    }
}

extern "C" void kernel_launch(void* const* d_in, const int* in_sizes, int n_in,
                              void* d_out, int out_size) {
    const float* p0   = (const float*)d_in[0];
    const float* p1   = (const float*)d_in[1];
    const float* p2   = (const float*)d_in[2];
    const float* gtb  = (const float*)d_in[3];
    const int*   gtl  = (const int*)d_in[4];
    const int*   mind = (const int*)d_in[5];
    float* out = (float*)d_out;

    // 800 + 200 + 50 = 1050 blocks; one wave at 8 blocks/SM
    yolo_loss_kernel<<<1050, 256>>>(p0, p1, p2, gtb, gtl, mind, out, out_size);
}